// round 8
// baseline (speedup 1.0000x reference)
#include <cuda_runtime.h>
#include <math.h>

// ---------------------------------------------------------------------------
// SwinBlock: LN1 -> shifted-window MHA (+rel-pos bias, +mask) -> proj ->
//            residual -> LN2 -> MLP(GELU exact) -> residual
// Shapes fixed: B=32, H=W=56, C=384, NH=12, hd=32, WS=7, SHIFT=3, HID=1536
// ---------------------------------------------------------------------------

#define NTOK   100352          // 32*3136 = 2048 windows * 49 tokens
#define CDIM   384
#define NHEAD  12
#define HD     32
#define N3     1152
#define HIDD   1536
#define FULLMASK 0xffffffffu

// ---------------- scratch (static device globals; no allocation) -----------
__device__ float g_bufA[NTOK * CDIM];   // LN1 windows, later LN2 output (h2)
__device__ float g_qkv [NTOK * N3];     // qkv
__device__ float g_att [NTOK * CDIM];   // attention output (window-token major)
__device__ float g_x1  [NTOK * CDIM];   // x + attn path (residual stream)
__device__ float g_hid [NTOK * HIDD];   // MLP hidden

// ---------------- packed f32x2 helpers -------------------------------------
__device__ __forceinline__ unsigned long long bcast2(float x) {
    unsigned long long r; unsigned u = __float_as_uint(x);
    asm("mov.b64 %0, {%1, %1};" : "=l"(r) : "r"(u));
    return r;
}
__device__ __forceinline__ void fma2(unsigned long long& c,
                                     unsigned long long a,
                                     unsigned long long b) {
    asm("fma.rn.f32x2 %0, %1, %2, %0;" : "+l"(c) : "l"(a), "l"(b));
}

// ---------------- LayerNorm (optionally fused roll + window partition) -----
// WINDOW=true: block b maps output token (window layout) -> source token in x
//   via inverse of: roll(-3,-3) then 7x7 window partition.
template<bool WINDOW>
__global__ __launch_bounds__(128)
void ln_kernel(const float* __restrict__ x, const float* __restrict__ g,
               const float* __restrict__ bta, float* __restrict__ out)
{
    __shared__ float sa[4], sb[4];
    const int token = blockIdx.x;
    size_t src;
    if (WINDOW) {
        int bwin  = token / 49;
        int n     = token - bwin * 49;
        int batch = bwin >> 6;          // / 64 windows per image
        int widx  = bwin & 63;
        int wh = widx >> 3, ww = widx & 7;
        int r = n / 7, c = n - r * 7;
        int fr = wh * 7 + r + 3; if (fr >= 56) fr -= 56;  // rolled[i]=x[(i+3)%56]
        int fc = ww * 7 + c + 3; if (fc >= 56) fc -= 56;
        src = (size_t)batch * 3136 + fr * 56 + fc;
    } else {
        src = token;
    }
    const float* xr = x + src * CDIM;
    const int tid = threadIdx.x;
    float v0 = xr[tid], v1 = xr[tid + 128], v2 = xr[tid + 256];
    float s  = v0 + v1 + v2;
    float s2 = v0 * v0 + v1 * v1 + v2 * v2;
    #pragma unroll
    for (int o = 16; o > 0; o >>= 1) {
        s  += __shfl_xor_sync(FULLMASK, s,  o);
        s2 += __shfl_xor_sync(FULLMASK, s2, o);
    }
    int w = tid >> 5;
    if ((tid & 31) == 0) { sa[w] = s; sb[w] = s2; }
    __syncthreads();
    s  = sa[0] + sa[1] + sa[2] + sa[3];
    s2 = sb[0] + sb[1] + sb[2] + sb[3];
    const float mean = s * (1.0f / 384.0f);
    const float var  = s2 * (1.0f / 384.0f) - mean * mean;
    const float rstd = rsqrtf(var + 1e-5f);
    float* orow = out + (size_t)token * CDIM;
    orow[tid]       = (v0 - mean) * rstd * g[tid]       + bta[tid];
    orow[tid + 128] = (v1 - mean) * rstd * g[tid + 128] + bta[tid + 128];
    orow[tid + 256] = (v2 - mean) * rstd * g[tid + 256] + bta[tid + 256];
}

// ---------------- GEMM: C = A(M,K) @ B(K,N) + bias, fused epilogues --------
// 128x128 tile, BK=8, 256 threads, 8x8 per thread, f32x2-packed FMA.
// EPI: 0 = bias only (qkv)
//      1 = bias + exact GELU (fc1)
//      2 = bias + window-reverse/roll scatter + residual x (proj)
//      3 = bias + residual (fc2 -> d_out)
template<int EPI>
__global__ __launch_bounds__(256, 2)
void gemm_kernel(const float* __restrict__ A, const float* __restrict__ B,
                 const float* __restrict__ bias, const float* __restrict__ res,
                 float* __restrict__ out, int N, int K)
{
    __shared__ __align__(16) float As[8][128];
    __shared__ __align__(16) float Bs[8][128];
    const int tid = threadIdx.x;
    const int tx = tid & 15, ty = tid >> 4;
    const int m0 = blockIdx.y << 7, n0 = blockIdx.x << 7;

    const int arow = tid >> 1, ak = (tid & 1) << 2;     // A: 128 rows x 8 cols
    const int brow = tid >> 5, bcol = (tid & 31) << 2;  // B: 8 rows x 128 cols
    const float* Ap = A + (size_t)(m0 + arow) * K + ak;
    const float* Bp = B + (size_t)brow * N + n0 + bcol;

    unsigned long long acc[8][4];
    #pragma unroll
    for (int i = 0; i < 8; i++)
        #pragma unroll
        for (int j = 0; j < 4; j++) acc[i][j] = 0ull;

    float4 av = *(const float4*)Ap;
    float4 bv = *(const float4*)Bp;

    for (int kk = 0; kk < K; kk += 8) {
        As[ak + 0][arow] = av.x; As[ak + 1][arow] = av.y;
        As[ak + 2][arow] = av.z; As[ak + 3][arow] = av.w;
        *(float4*)&Bs[brow][bcol] = bv;
        __syncthreads();
        if (kk + 8 < K) {   // software prefetch of next tiles
            av = *(const float4*)(Ap + kk + 8);
            bv = *(const float4*)(Bp + (size_t)(kk + 8) * N);
        }
        #pragma unroll
        for (int k = 0; k < 8; k++) {
            unsigned long long bp[4], ap[8];
            const unsigned long long* br =
                (const unsigned long long*)&Bs[k][tx << 3];
            #pragma unroll
            for (int j = 0; j < 4; j++) bp[j] = br[j];
            #pragma unroll
            for (int i = 0; i < 8; i++) ap[i] = bcast2(As[k][(ty << 3) + i]);
            #pragma unroll
            for (int i = 0; i < 8; i++)
                #pragma unroll
                for (int j = 0; j < 4; j++) fma2(acc[i][j], ap[i], bp[j]);
        }
        __syncthreads();
    }

    #pragma unroll
    for (int i = 0; i < 8; i++) {
        const int gm = m0 + (ty << 3) + i;
        size_t obase;
        if (EPI == 2) {
            // row gm is window-token (bwin, n) -> scatter to (batch, fr, fc)
            int bwin  = gm / 49;
            int n     = gm - bwin * 49;
            int batch = bwin >> 6;
            int widx  = bwin & 63;
            int wh = widx >> 3, ww = widx & 7;
            int r = n / 7, c = n - r * 7;
            int fr = wh * 7 + r + 3; if (fr >= 56) fr -= 56;
            int fc = ww * 7 + c + 3; if (fc >= 56) fc -= 56;
            obase = ((size_t)batch * 3136 + fr * 56 + fc) * CDIM;
        } else {
            obase = (size_t)gm * N;
        }
        #pragma unroll
        for (int j = 0; j < 4; j++) {
            const int gn = n0 + (tx << 3) + (j << 1);
            float lo = __uint_as_float((unsigned)(acc[i][j] & 0xffffffffull));
            float hi = __uint_as_float((unsigned)(acc[i][j] >> 32));
            lo += bias[gn]; hi += bias[gn + 1];
            if (EPI == 1) {   // exact GELU
                lo = 0.5f * lo * (1.0f + erff(lo * 0.70710678118654752f));
                hi = 0.5f * hi * (1.0f + erff(hi * 0.70710678118654752f));
            }
            if (EPI == 2 || EPI == 3) {
                float2 rv = *(const float2*)(res + obase + gn);
                lo += rv.x; hi += rv.y;
            }
            float2 o; o.x = lo; o.y = hi;
            *(float2*)(out + obase + gn) = o;
        }
    }
}

// ---------------- windowed attention: one block per (window, head) ---------
// scores = scale*q@k^T + rel_pos_bias[h] + mask[b%64]; softmax; out = p@v
__global__ __launch_bounds__(256)
void attn_kernel(const float* __restrict__ qkv, const float* __restrict__ rpb,
                 const float* __restrict__ mask, float* __restrict__ out)
{
    __shared__ float qs[49 * 32];
    __shared__ float ks[49 * 33];   // padded stride 33: conflict-free k reads
    __shared__ float vs[49 * 32];
    __shared__ float sc[49 * 49];

    const int b = blockIdx.y;       // window 0..2047
    const int h = blockIdx.x;       // head 0..11
    const int tid = threadIdx.x;

    const float* base = qkv + (size_t)b * 49 * N3 + h * HD;
    for (int idx = tid; idx < 49 * 32; idx += 256) {
        int n = idx >> 5, d = idx & 31;
        const float* row = base + (size_t)n * N3;
        qs[idx]         = row[d];
        ks[n * 33 + d]  = row[384 + d];
        vs[idx]         = row[768 + d];
    }
    __syncthreads();

    const float scale = 0.17677669529663687f;  // 1/sqrt(32)
    const float* mrow = mask + (size_t)(b & 63) * 2401;
    for (int idx = tid; idx < 2401; idx += 256) {
        int n = idx / 49, m = idx - n * 49;
        const float* qn = qs + n * 32;
        const float* km = ks + m * 33;
        float s = 0.0f;
        #pragma unroll
        for (int d = 0; d < 32; d++) s += qn[d] * km[d];
        int r1 = n / 7, c1 = n - r1 * 7;
        int r2 = m / 7, c2 = m - r2 * 7;
        int ridx = (r1 - r2 + 6) * 13 + (c1 - c2 + 6);
        sc[idx] = s * scale + rpb[ridx * NHEAD + h] + mrow[idx];
    }
    __syncthreads();

    const int warp = tid >> 5, lane = tid & 31;
    for (int row = warp; row < 49; row += 8) {
        float* sr = sc + row * 49;
        float v0 = sr[lane];
        float v1 = (lane + 32 < 49) ? sr[lane + 32] : -1e30f;
        float mx = fmaxf(v0, v1);
        #pragma unroll
        for (int o = 16; o > 0; o >>= 1) mx = fmaxf(mx, __shfl_xor_sync(FULLMASK, mx, o));
        float e0 = __expf(v0 - mx);
        float e1 = (lane + 32 < 49) ? __expf(v1 - mx) : 0.0f;
        float sm = e0 + e1;
        #pragma unroll
        for (int o = 16; o > 0; o >>= 1) sm += __shfl_xor_sync(FULLMASK, sm, o);
        float inv = 1.0f / sm;
        sr[lane] = e0 * inv;
        if (lane + 32 < 49) sr[lane + 32] = e1 * inv;
    }
    __syncthreads();

    for (int idx = tid; idx < 49 * 32; idx += 256) {
        int n = idx >> 5, d = idx & 31;
        const float* pr = sc + n * 49;
        float s = 0.0f;
        #pragma unroll 7
        for (int m = 0; m < 49; m++) s += pr[m] * vs[m * 32 + d];
        out[(size_t)(b * 49 + n) * CDIM + h * HD + d] = s;
    }
}

// ---------------------------------------------------------------------------
extern "C" void kernel_launch(void* const* d_in, const int* in_sizes, int n_in,
                              void* d_out, int out_size)
{
    const float* x     = (const float*)d_in[0];
    const float* amask = (const float*)d_in[1];
    const float* n1g   = (const float*)d_in[2];
    const float* n1b   = (const float*)d_in[3];
    const float* qkvW  = (const float*)d_in[4];
    const float* qkvB  = (const float*)d_in[5];
    const float* rpb   = (const float*)d_in[6];
    const float* projW = (const float*)d_in[7];
    const float* projB = (const float*)d_in[8];
    const float* n2g   = (const float*)d_in[9];
    const float* n2b   = (const float*)d_in[10];
    const float* fc1W  = (const float*)d_in[11];
    const float* fc1B  = (const float*)d_in[12];
    const float* fc2W  = (const float*)d_in[13];
    const float* fc2B  = (const float*)d_in[14];
    float* out = (float*)d_out;

    float *bufA, *qkv, *att, *x1, *hid;
    cudaGetSymbolAddress((void**)&bufA, g_bufA);
    cudaGetSymbolAddress((void**)&qkv,  g_qkv);
    cudaGetSymbolAddress((void**)&att,  g_att);
    cudaGetSymbolAddress((void**)&x1,   g_x1);
    cudaGetSymbolAddress((void**)&hid,  g_hid);

    // 1. LN1 + roll(-3,-3) + window partition  -> bufA (windowed tokens)
    ln_kernel<true><<<NTOK, 128>>>(x, n1g, n1b, bufA);
    // 2. qkv = bufA @ qkv_w + qkv_b            (100352 x 1152, K=384)
    gemm_kernel<0><<<dim3(9, 784), 256>>>(bufA, qkvW, qkvB, nullptr, qkv, N3, CDIM);
    // 3. windowed attention                    -> att
    attn_kernel<<<dim3(NHEAD, 2048), 256>>>(qkv, rpb, amask, att);
    // 4. proj + window-reverse/roll scatter + residual(x) -> x1
    gemm_kernel<2><<<dim3(3, 784), 256>>>(att, projW, projB, x, x1, CDIM, CDIM);
    // 5. LN2                                   -> bufA (h2)
    ln_kernel<false><<<NTOK, 128>>>(x1, n2g, n2b, bufA);
    // 6. fc1 + GELU                            -> hid (100352 x 1536, K=384)
    gemm_kernel<1><<<dim3(12, 784), 256>>>(bufA, fc1W, fc1B, nullptr, hid, HIDD, CDIM);
    // 7. fc2 + residual(x1)                    -> d_out (100352 x 384, K=1536)
    gemm_kernel<3><<<dim3(3, 784), 256>>>(hid, fc2W, fc2B, x1, out, CDIM, HIDD);
}

// round 11
// speedup vs baseline: 2.0173x; 2.0173x over previous
#include <cuda_runtime.h>
#include <cuda_bf16.h>
#include <math.h>
#include <stdint.h>

// ---------------------------------------------------------------------------
// SwinBlock with all four GEMMs on HMMA (mma.sync m16n8k16 bf16, fp32 acc),
// bf16 hi/lo split 3-term for ~1e-5 rel err. tcgen05 is unavailable: the
// harness's PTX stage targets base sm_103 (no 'a' features).
// Shapes fixed: B=32, H=W=56, C=384, NH=12, hd=32, WS=7, SHIFT=3, HID=1536
// ---------------------------------------------------------------------------

#define NTOK   100352          // 2048 windows * 49 tokens
#define CDIM   384
#define NHEAD  12
#define HD     32
#define N3     1152
#define HIDD   1536
#define FULLMASK 0xffffffffu

// GEMM tiling: CTA 128x128, BK=64, 2-stage cp.async pipeline
#define BK       64
#define ROWB     144                       // 64 bf16 = 128B, padded to 144B
#define TBYTES   (128 * ROWB)              // 18432 per tensor tile
#define STAGEB   (4 * TBYTES)              // Ahi, Alo, Bhi, Blo
#define SMEM_TOTAL (2 * STAGEB)            // 147456 B dynamic smem

// ---------------- scratch (static device globals; no allocation) -----------
__device__ float          g_qkv [(size_t)NTOK * N3];    // fp32 qkv
__device__ float          g_x1  [(size_t)NTOK * CDIM];  // residual stream
__device__ __nv_bfloat16  g_ahi [(size_t)NTOK * CDIM];  // activation hi (reused)
__device__ __nv_bfloat16  g_alo [(size_t)NTOK * CDIM];  // activation lo
__device__ __nv_bfloat16  g_hhi [(size_t)NTOK * HIDD];  // MLP hidden hi
__device__ __nv_bfloat16  g_hlo [(size_t)NTOK * HIDD];  // MLP hidden lo
// transposed+split weights: Wt[N][K]
__device__ __nv_bfloat16  g_wqkv_hi[N3  * CDIM], g_wqkv_lo[N3  * CDIM];
__device__ __nv_bfloat16  g_wprj_hi[CDIM* CDIM], g_wprj_lo[CDIM* CDIM];
__device__ __nv_bfloat16  g_wfc1_hi[HIDD* CDIM], g_wfc1_lo[HIDD* CDIM];
__device__ __nv_bfloat16  g_wfc2_hi[CDIM* HIDD], g_wfc2_lo[CDIM* HIDD];

// ---------------- PTX helpers ----------------------------------------------
__device__ __forceinline__ uint32_t smem_u32(const void* p) {
    uint32_t a;
    asm("{ .reg .u64 t; cvta.to.shared.u64 t, %1; cvt.u32.u64 %0, t; }"
        : "=r"(a) : "l"(p));
    return a;
}
__device__ __forceinline__ void ldm_x4(uint32_t* r, uint32_t a) {
    asm volatile("ldmatrix.sync.aligned.m8n8.x4.shared.b16 {%0,%1,%2,%3}, [%4];"
                 : "=r"(r[0]), "=r"(r[1]), "=r"(r[2]), "=r"(r[3]) : "r"(a));
}
__device__ __forceinline__ void mma_bf16(float* c, const uint32_t* a,
                                         uint32_t b0, uint32_t b1) {
    asm volatile("mma.sync.aligned.m16n8k16.row.col.f32.bf16.bf16.f32 "
                 "{%0,%1,%2,%3}, {%4,%5,%6,%7}, {%8,%9}, {%0,%1,%2,%3};"
                 : "+f"(c[0]), "+f"(c[1]), "+f"(c[2]), "+f"(c[3])
                 : "r"(a[0]), "r"(a[1]), "r"(a[2]), "r"(a[3]), "r"(b0), "r"(b1));
}
__device__ __forceinline__ void cp16(uint32_t sa, const void* ga) {
    asm volatile("cp.async.cg.shared.global [%0], [%1], 16;" :: "r"(sa), "l"(ga));
}
#define CP_COMMIT()  asm volatile("cp.async.commit_group;")
#define CP_WAIT(n)   asm volatile("cp.async.wait_group %0;" :: "n"(n))

__device__ __forceinline__ void split_bf16(float v, __nv_bfloat16& h, __nv_bfloat16& l) {
    h = __float2bfloat16(v);
    l = __float2bfloat16(v - __bfloat162float(h));
}

// ---------------- weight transpose + split: W[K][N] -> Wt[N][K] hi/lo ------
__global__ void wsplitT(const float* __restrict__ W, __nv_bfloat16* __restrict__ hi,
                        __nv_bfloat16* __restrict__ lo, int K, int N)
{
    int idx = blockIdx.x * 256 + threadIdx.x;
    if (idx >= K * N) return;
    int n = idx / K, k = idx - n * K;
    float w = W[(size_t)k * N + n];
    __nv_bfloat16 h, l; split_bf16(w, h, l);
    hi[idx] = h; lo[idx] = l;
}

// ---------------- LayerNorm (optionally fused roll + window partition) -----
template<bool WINDOW>
__global__ __launch_bounds__(128)
void ln_kernel(const float* __restrict__ x, const float* __restrict__ g,
               const float* __restrict__ bta,
               __nv_bfloat16* __restrict__ ohi, __nv_bfloat16* __restrict__ olo)
{
    __shared__ float sa[4], sb[4];
    const int token = blockIdx.x;
    size_t src;
    if (WINDOW) {
        int bwin  = token / 49;
        int n     = token - bwin * 49;
        int batch = bwin >> 6;
        int widx  = bwin & 63;
        int wh = widx >> 3, ww = widx & 7;
        int r = n / 7, c = n - r * 7;
        int fr = wh * 7 + r + 3; if (fr >= 56) fr -= 56;
        int fc = ww * 7 + c + 3; if (fc >= 56) fc -= 56;
        src = (size_t)batch * 3136 + fr * 56 + fc;
    } else {
        src = token;
    }
    const float* xr = x + src * CDIM;
    const int tid = threadIdx.x;
    float v0 = xr[tid], v1 = xr[tid + 128], v2 = xr[tid + 256];
    float s  = v0 + v1 + v2;
    float s2 = v0 * v0 + v1 * v1 + v2 * v2;
    #pragma unroll
    for (int o = 16; o > 0; o >>= 1) {
        s  += __shfl_xor_sync(FULLMASK, s,  o);
        s2 += __shfl_xor_sync(FULLMASK, s2, o);
    }
    int w = tid >> 5;
    if ((tid & 31) == 0) { sa[w] = s; sb[w] = s2; }
    __syncthreads();
    s  = sa[0] + sa[1] + sa[2] + sa[3];
    s2 = sb[0] + sb[1] + sb[2] + sb[3];
    const float mean = s * (1.0f / 384.0f);
    const float var  = s2 * (1.0f / 384.0f) - mean * mean;
    const float rstd = rsqrtf(var + 1e-5f);
    size_t ob = (size_t)token * CDIM;
    #pragma unroll
    for (int e = 0; e < 3; e++) {
        int c = tid + e * 128;
        float v = (e == 0 ? v0 : e == 1 ? v1 : v2);
        float y = (v - mean) * rstd * g[c] + bta[c];
        __nv_bfloat16 h, l; split_bf16(y, h, l);
        ohi[ob + c] = h; olo[ob + c] = l;
    }
}

// ---------------- windowed attention: one block per (window, head) ---------
__global__ __launch_bounds__(256)
void attn_kernel(const float* __restrict__ qkv, const float* __restrict__ rpb,
                 const float* __restrict__ mask,
                 __nv_bfloat16* __restrict__ ohi, __nv_bfloat16* __restrict__ olo)
{
    __shared__ float qs[49 * 32];
    __shared__ float ks[49 * 33];
    __shared__ float vs[49 * 32];
    __shared__ float sc[49 * 49];

    const int b = blockIdx.y;
    const int h = blockIdx.x;
    const int tid = threadIdx.x;

    const float* base = qkv + (size_t)b * 49 * N3 + h * HD;
    for (int idx = tid; idx < 49 * 32; idx += 256) {
        int n = idx >> 5, d = idx & 31;
        const float* row = base + (size_t)n * N3;
        qs[idx]        = row[d];
        ks[n * 33 + d] = row[384 + d];
        vs[idx]        = row[768 + d];
    }
    __syncthreads();

    const float scale = 0.17677669529663687f;
    const float* mrow = mask + (size_t)(b & 63) * 2401;
    for (int idx = tid; idx < 2401; idx += 256) {
        int n = idx / 49, m = idx - n * 49;
        const float* qn = qs + n * 32;
        const float* km = ks + m * 33;
        float s = 0.0f;
        #pragma unroll
        for (int d = 0; d < 32; d++) s += qn[d] * km[d];
        int r1 = n / 7, c1 = n - r1 * 7;
        int r2 = m / 7, c2 = m - r2 * 7;
        int ridx = (r1 - r2 + 6) * 13 + (c1 - c2 + 6);
        sc[idx] = s * scale + rpb[ridx * NHEAD + h] + mrow[idx];
    }
    __syncthreads();

    const int warp = tid >> 5, lane = tid & 31;
    for (int row = warp; row < 49; row += 8) {
        float* sr = sc + row * 49;
        float v0 = sr[lane];
        float v1 = (lane + 32 < 49) ? sr[lane + 32] : -1e30f;
        float mx = fmaxf(v0, v1);
        #pragma unroll
        for (int o = 16; o > 0; o >>= 1) mx = fmaxf(mx, __shfl_xor_sync(FULLMASK, mx, o));
        float e0 = __expf(v0 - mx);
        float e1 = (lane + 32 < 49) ? __expf(v1 - mx) : 0.0f;
        float sm = e0 + e1;
        #pragma unroll
        for (int o = 16; o > 0; o >>= 1) sm += __shfl_xor_sync(FULLMASK, sm, o);
        float inv = 1.0f / sm;
        sr[lane] = e0 * inv;
        if (lane + 32 < 49) sr[lane + 32] = e1 * inv;
    }
    __syncthreads();

    for (int idx = tid; idx < 49 * 32; idx += 256) {
        int n = idx >> 5, d = idx & 31;
        const float* pr = sc + n * 49;
        float s = 0.0f;
        #pragma unroll 7
        for (int m = 0; m < 49; m++) s += pr[m] * vs[m * 32 + d];
        size_t off = (size_t)(b * 49 + n) * CDIM + h * HD + d;
        __nv_bfloat16 hh, ll; split_bf16(s, hh, ll);
        ohi[off] = hh; olo[off] = ll;
    }
}

// ---------------- HMMA GEMM: C = A(M,K) @ Bt(N,K)^T + bias, fused epi ------
// bf16 hi/lo split, 3 mma.sync terms per frag. 8 warps (2x4), warp 64x32.
// EPI: 0 = bias -> fp32 (qkv)     1 = bias + GELU -> bf16 hi/lo (fc1)
//      2 = bias + window-reverse scatter + residual -> fp32 (proj)
//      3 = bias + residual -> fp32 (fc2 -> d_out)
template<int EPI>
__global__ __launch_bounds__(256, 1)
void gemm_tc(const __nv_bfloat16* __restrict__ Ahi, const __nv_bfloat16* __restrict__ Alo,
             const __nv_bfloat16* __restrict__ Bhi, const __nv_bfloat16* __restrict__ Blo,
             const float* __restrict__ bias, const float* __restrict__ res,
             float* __restrict__ outf,
             __nv_bfloat16* __restrict__ ohi, __nv_bfloat16* __restrict__ olo,
             int N, int K)
{
    extern __shared__ __align__(128) char smem[];
    const uint32_t sbase = smem_u32(smem);
    const int tid  = threadIdx.x;
    const int wid  = tid >> 5, lane = tid & 31;
    const int warp_m = wid & 1, warp_n = wid >> 1;
    const int m0 = blockIdx.y << 7, n0 = blockIdx.x << 7;
    const int nc = K >> 6;

    float acc[4][4][4];
    #pragma unroll
    for (int i = 0; i < 4; i++)
        #pragma unroll
        for (int j = 0; j < 4; j++)
            #pragma unroll
            for (int e = 0; e < 4; e++) acc[i][j][e] = 0.0f;

    auto load_chunk = [&](int k0, int st) {
        const uint32_t so = sbase + st * STAGEB;
        #pragma unroll
        for (int t = 0; t < 4; t++) {
            const __nv_bfloat16* gb = (t == 0 ? Ahi : t == 1 ? Alo : t == 2 ? Bhi : Blo);
            const int rb = (t < 2 ? m0 : n0);
            #pragma unroll
            for (int it = 0; it < 4; it++) {
                int slot = (it << 8) + tid;          // 0..1023
                int row = slot >> 3, seg = slot & 7;
                cp16(so + t * TBYTES + row * ROWB + (seg << 4),
                     gb + (size_t)(rb + row) * K + k0 + (seg << 3));
            }
        }
        CP_COMMIT();
    };

    load_chunk(0, 0);

    for (int c = 0; c < nc; c++) {
        if (c + 1 < nc) { load_chunk((c + 1) << 6, (c + 1) & 1); CP_WAIT(1); }
        else            { CP_WAIT(0); }
        __syncthreads();

        const uint32_t sA  = sbase + (c & 1) * STAGEB;
        const uint32_t sAl = sA + TBYTES;
        const uint32_t sB  = sA + 2 * TBYTES;
        const uint32_t sBl = sA + 3 * TBYTES;
        const int arow = (lane & 7) + (lane & 8);           // ldmatrix A row map
        const int acol = ((lane >> 4) << 3);
        const int brow = (lane & 7) + ((lane >> 1) & 8);    // ldmatrix B row map
        const int bcol = (lane & 8);

        #pragma unroll
        for (int ks = 0; ks < 4; ks++) {
            const int kb = ks << 4;
            uint32_t ah[4][4], al[4][4];
            #pragma unroll
            for (int mf = 0; mf < 4; mf++) {
                uint32_t off = (warp_m * 64 + mf * 16 + arow) * ROWB + (kb + acol) * 2;
                ldm_x4(ah[mf], sA  + off);
                ldm_x4(al[mf], sAl + off);
            }
            uint32_t bh[2][4], bl[2][4];
            #pragma unroll
            for (int nt = 0; nt < 2; nt++) {
                uint32_t off = (warp_n * 32 + nt * 16 + brow) * ROWB + (kb + bcol) * 2;
                ldm_x4(bh[nt], sB  + off);
                ldm_x4(bl[nt], sBl + off);
            }
            #pragma unroll
            for (int mf = 0; mf < 4; mf++)
                #pragma unroll
                for (int nf = 0; nf < 4; nf++) {
                    const int nt = nf >> 1, bs = (nf & 1) << 1;
                    mma_bf16(acc[mf][nf], ah[mf], bh[nt][bs], bh[nt][bs + 1]);
                    mma_bf16(acc[mf][nf], ah[mf], bl[nt][bs], bl[nt][bs + 1]);
                    mma_bf16(acc[mf][nf], al[mf], bh[nt][bs], bh[nt][bs + 1]);
                }
        }
        __syncthreads();
    }

    // ---------------- epilogue ---------------------------------------------
    #pragma unroll
    for (int mf = 0; mf < 4; mf++) {
        #pragma unroll
        for (int hh = 0; hh < 2; hh++) {
            const int gm = m0 + warp_m * 64 + mf * 16 + (lane >> 2) + hh * 8;
            size_t obase;
            if (EPI == 2) {
                int bwin  = gm / 49;
                int n     = gm - bwin * 49;
                int batch = bwin >> 6;
                int widx  = bwin & 63;
                int wh = widx >> 3, ww = widx & 7;
                int r = n / 7, cc = n - r * 7;
                int fr = wh * 7 + r + 3;  if (fr >= 56) fr -= 56;
                int fc = ww * 7 + cc + 3; if (fc >= 56) fc -= 56;
                obase = ((size_t)batch * 3136 + fr * 56 + fc) * CDIM;
            } else {
                obase = (size_t)gm * N;
            }
            #pragma unroll
            for (int nf = 0; nf < 4; nf++) {
                const int gn = n0 + warp_n * 32 + nf * 8 + ((lane & 3) << 1);
                float v0 = acc[mf][nf][hh * 2 + 0];
                float v1 = acc[mf][nf][hh * 2 + 1];
                float2 bv = *(const float2*)(bias + gn);
                v0 += bv.x; v1 += bv.y;
                if (EPI == 1) {
                    v0 = 0.5f * v0 * (1.0f + erff(v0 * 0.70710678118654752f));
                    v1 = 0.5f * v1 * (1.0f + erff(v1 * 0.70710678118654752f));
                    __nv_bfloat16 h0, l0, h1, l1;
                    split_bf16(v0, h0, l0); split_bf16(v1, h1, l1);
                    __nv_bfloat162 hp; hp.x = h0; hp.y = h1;
                    __nv_bfloat162 lp; lp.x = l0; lp.y = l1;
                    *(__nv_bfloat162*)(ohi + obase + gn) = hp;
                    *(__nv_bfloat162*)(olo + obase + gn) = lp;
                } else {
                    if (EPI == 2 || EPI == 3) {
                        float2 rv = *(const float2*)(res + obase + gn);
                        v0 += rv.x; v1 += rv.y;
                    }
                    float2 o; o.x = v0; o.y = v1;
                    *(float2*)(outf + obase + gn) = o;
                }
            }
        }
    }
}

// ---------------------------------------------------------------------------
extern "C" void kernel_launch(void* const* d_in, const int* in_sizes, int n_in,
                              void* d_out, int out_size)
{
    const float* x     = (const float*)d_in[0];
    const float* amask = (const float*)d_in[1];
    const float* n1g   = (const float*)d_in[2];
    const float* n1b   = (const float*)d_in[3];
    const float* qkvW  = (const float*)d_in[4];
    const float* qkvB  = (const float*)d_in[5];
    const float* rpb   = (const float*)d_in[6];
    const float* projW = (const float*)d_in[7];
    const float* projB = (const float*)d_in[8];
    const float* n2g   = (const float*)d_in[9];
    const float* n2b   = (const float*)d_in[10];
    const float* fc1W  = (const float*)d_in[11];
    const float* fc1B  = (const float*)d_in[12];
    const float* fc2W  = (const float*)d_in[13];
    const float* fc2B  = (const float*)d_in[14];
    float* out = (float*)d_out;

    float *qkv, *x1;
    __nv_bfloat16 *ahi, *alo, *hhi, *hlo;
    __nv_bfloat16 *wqh, *wql, *wph, *wpl, *w1h, *w1l, *w2h, *w2l;
    cudaGetSymbolAddress((void**)&qkv, g_qkv);
    cudaGetSymbolAddress((void**)&x1,  g_x1);
    cudaGetSymbolAddress((void**)&ahi, g_ahi);
    cudaGetSymbolAddress((void**)&alo, g_alo);
    cudaGetSymbolAddress((void**)&hhi, g_hhi);
    cudaGetSymbolAddress((void**)&hlo, g_hlo);
    cudaGetSymbolAddress((void**)&wqh, g_wqkv_hi);
    cudaGetSymbolAddress((void**)&wql, g_wqkv_lo);
    cudaGetSymbolAddress((void**)&wph, g_wprj_hi);
    cudaGetSymbolAddress((void**)&wpl, g_wprj_lo);
    cudaGetSymbolAddress((void**)&w1h, g_wfc1_hi);
    cudaGetSymbolAddress((void**)&w1l, g_wfc1_lo);
    cudaGetSymbolAddress((void**)&w2h, g_wfc2_hi);
    cudaGetSymbolAddress((void**)&w2l, g_wfc2_lo);

    cudaFuncSetAttribute(gemm_tc<0>, cudaFuncAttributeMaxDynamicSharedMemorySize, SMEM_TOTAL);
    cudaFuncSetAttribute(gemm_tc<1>, cudaFuncAttributeMaxDynamicSharedMemorySize, SMEM_TOTAL);
    cudaFuncSetAttribute(gemm_tc<2>, cudaFuncAttributeMaxDynamicSharedMemorySize, SMEM_TOTAL);
    cudaFuncSetAttribute(gemm_tc<3>, cudaFuncAttributeMaxDynamicSharedMemorySize, SMEM_TOTAL);

    // 0. weight transpose + bf16 split (tiny)
    wsplitT<<<(N3  * CDIM + 255) / 256, 256>>>(qkvW, wqh, wql, CDIM, N3);
    wsplitT<<<(CDIM* CDIM + 255) / 256, 256>>>(projW, wph, wpl, CDIM, CDIM);
    wsplitT<<<(HIDD* CDIM + 255) / 256, 256>>>(fc1W, w1h, w1l, CDIM, HIDD);
    wsplitT<<<(CDIM* HIDD + 255) / 256, 256>>>(fc2W, w2h, w2l, HIDD, CDIM);

    // 1. LN1 + roll + window partition -> bf16 hi/lo
    ln_kernel<true><<<NTOK, 128>>>(x, n1g, n1b, ahi, alo);
    // 2. qkv GEMM (N=1152, K=384) -> fp32
    gemm_tc<0><<<dim3(9, 784), 256, SMEM_TOTAL>>>(ahi, alo, wqh, wql, qkvB,
                                                  nullptr, qkv, nullptr, nullptr, N3, CDIM);
    // 3. windowed attention -> bf16 hi/lo (reuse a-buffers)
    attn_kernel<<<dim3(NHEAD, 2048), 256>>>(qkv, rpb, amask, ahi, alo);
    // 4. proj GEMM + window-reverse scatter + residual(x) -> x1
    gemm_tc<2><<<dim3(3, 784), 256, SMEM_TOTAL>>>(ahi, alo, wph, wpl, projB,
                                                  x, x1, nullptr, nullptr, CDIM, CDIM);
    // 5. LN2 -> bf16 hi/lo
    ln_kernel<false><<<NTOK, 128>>>(x1, n2g, n2b, ahi, alo);
    // 6. fc1 GEMM + GELU -> bf16 hi/lo hidden
    gemm_tc<1><<<dim3(12, 784), 256, SMEM_TOTAL>>>(ahi, alo, w1h, w1l, fc1B,
                                                   nullptr, nullptr, hhi, hlo, HIDD, CDIM);
    // 7. fc2 GEMM + residual(x1) -> d_out
    gemm_tc<3><<<dim3(3, 784), 256, SMEM_TOTAL>>>(hhi, hlo, w2h, w2l, fc2B,
                                                  x1, out, nullptr, nullptr, CDIM, HIDD);
}

// round 12
// speedup vs baseline: 3.6382x; 1.8035x over previous
#include <cuda_runtime.h>
#include <cuda_fp16.h>
#include <math.h>
#include <stdint.h>

// ---------------------------------------------------------------------------
// SwinBlock, all four GEMMs on HMMA mma.sync m16n8k16 fp16 (fp32 acc),
// single-term fp16 operands (rel-err ~1e-4, budget 1e-3).
// 3-stage cp.async pipeline, 2 CTAs/SM.
// Shapes fixed: B=32, H=W=56, C=384, NH=12, hd=32, WS=7, SHIFT=3, HID=1536
// ---------------------------------------------------------------------------

#define NTOK   100352          // 2048 windows * 49 tokens
#define CDIM   384
#define NHEAD  12
#define HD     32
#define N3     1152
#define HIDD   1536
#define FULLMASK 0xffffffffu

// GEMM tiling: CTA 128x128, BK=64, 3-stage cp.async pipeline
#define BK       64
#define ROWB     144                       // 64 fp16 = 128B, padded to 144B
#define TBYTES   (128 * ROWB)              // 18432 per tensor tile
#define STAGEB   (2 * TBYTES)              // A tile + B tile = 36864
#define NSTAGE   3
#define SMEM_TOTAL (NSTAGE * STAGEB)       // 110592 B dynamic smem

// ---------------- scratch (static device globals; no allocation) -----------
__device__ float   g_qkv[(size_t)NTOK * N3];    // fp32 qkv
__device__ float   g_x1 [(size_t)NTOK * CDIM];  // residual stream
__device__ __half  g_a  [(size_t)NTOK * CDIM];  // fp16 activations (reused)
__device__ __half  g_h  [(size_t)NTOK * HIDD];  // fp16 MLP hidden
// transposed fp16 weights: Wt[N][K]
__device__ __half  g_wqkv[N3  * CDIM];
__device__ __half  g_wprj[CDIM* CDIM];
__device__ __half  g_wfc1[HIDD* CDIM];
__device__ __half  g_wfc2[CDIM* HIDD];

// ---------------- PTX helpers ----------------------------------------------
__device__ __forceinline__ uint32_t smem_u32(const void* p) {
    uint32_t a;
    asm("{ .reg .u64 t; cvta.to.shared.u64 t, %1; cvt.u32.u64 %0, t; }"
        : "=r"(a) : "l"(p));
    return a;
}
__device__ __forceinline__ void ldm_x4(uint32_t* r, uint32_t a) {
    asm volatile("ldmatrix.sync.aligned.m8n8.x4.shared.b16 {%0,%1,%2,%3}, [%4];"
                 : "=r"(r[0]), "=r"(r[1]), "=r"(r[2]), "=r"(r[3]) : "r"(a));
}
__device__ __forceinline__ void mma_f16(float* c, const uint32_t* a,
                                        uint32_t b0, uint32_t b1) {
    asm volatile("mma.sync.aligned.m16n8k16.row.col.f32.f16.f16.f32 "
                 "{%0,%1,%2,%3}, {%4,%5,%6,%7}, {%8,%9}, {%0,%1,%2,%3};"
                 : "+f"(c[0]), "+f"(c[1]), "+f"(c[2]), "+f"(c[3])
                 : "r"(a[0]), "r"(a[1]), "r"(a[2]), "r"(a[3]), "r"(b0), "r"(b1));
}
__device__ __forceinline__ void cp16(uint32_t sa, const void* ga) {
    asm volatile("cp.async.cg.shared.global [%0], [%1], 16;" :: "r"(sa), "l"(ga));
}
#define CP_COMMIT()  asm volatile("cp.async.commit_group;")
#define CP_WAIT(n)   asm volatile("cp.async.wait_group %0;" :: "n"(n))

// ---------------- weight transpose to fp16: W[K][N] -> Wt[N][K] -------------
__global__ void wT(const float* __restrict__ W, __half* __restrict__ o, int K, int N)
{
    int idx = blockIdx.x * 256 + threadIdx.x;
    if (idx >= K * N) return;
    int n = idx / K, k = idx - n * K;
    o[idx] = __float2half_rn(W[(size_t)k * N + n]);
}

// ---------------- LayerNorm (optionally fused roll + window partition) -----
template<bool WINDOW>
__global__ __launch_bounds__(128)
void ln_kernel(const float* __restrict__ x, const float* __restrict__ g,
               const float* __restrict__ bta, __half* __restrict__ o)
{
    __shared__ float sa[4], sb[4];
    const int token = blockIdx.x;
    size_t src;
    if (WINDOW) {
        int bwin  = token / 49;
        int n     = token - bwin * 49;
        int batch = bwin >> 6;
        int widx  = bwin & 63;
        int wh = widx >> 3, ww = widx & 7;
        int r = n / 7, c = n - r * 7;
        int fr = wh * 7 + r + 3; if (fr >= 56) fr -= 56;
        int fc = ww * 7 + c + 3; if (fc >= 56) fc -= 56;
        src = (size_t)batch * 3136 + fr * 56 + fc;
    } else {
        src = token;
    }
    const float* xr = x + src * CDIM;
    const int tid = threadIdx.x;
    float v0 = xr[tid], v1 = xr[tid + 128], v2 = xr[tid + 256];
    float s  = v0 + v1 + v2;
    float s2 = v0 * v0 + v1 * v1 + v2 * v2;
    #pragma unroll
    for (int o2 = 16; o2 > 0; o2 >>= 1) {
        s  += __shfl_xor_sync(FULLMASK, s,  o2);
        s2 += __shfl_xor_sync(FULLMASK, s2, o2);
    }
    int w = tid >> 5;
    if ((tid & 31) == 0) { sa[w] = s; sb[w] = s2; }
    __syncthreads();
    s  = sa[0] + sa[1] + sa[2] + sa[3];
    s2 = sb[0] + sb[1] + sb[2] + sb[3];
    const float mean = s * (1.0f / 384.0f);
    const float var  = s2 * (1.0f / 384.0f) - mean * mean;
    const float rstd = rsqrtf(var + 1e-5f);
    size_t ob = (size_t)token * CDIM;
    o[ob + tid]       = __float2half_rn((v0 - mean) * rstd * g[tid]       + bta[tid]);
    o[ob + tid + 128] = __float2half_rn((v1 - mean) * rstd * g[tid + 128] + bta[tid + 128]);
    o[ob + tid + 256] = __float2half_rn((v2 - mean) * rstd * g[tid + 256] + bta[tid + 256]);
}

// ---------------- windowed attention: one block per (window, head) ---------
__global__ __launch_bounds__(256)
void attn_kernel(const float* __restrict__ qkv, const float* __restrict__ rpb,
                 const float* __restrict__ mask, __half* __restrict__ o)
{
    __shared__ float qs[49 * 32];
    __shared__ float ks[49 * 33];
    __shared__ float vs[49 * 32];
    __shared__ float sc[49 * 49];

    const int b = blockIdx.y;
    const int h = blockIdx.x;
    const int tid = threadIdx.x;

    const float* base = qkv + (size_t)b * 49 * N3 + h * HD;
    for (int idx = tid; idx < 49 * 32; idx += 256) {
        int n = idx >> 5, d = idx & 31;
        const float* row = base + (size_t)n * N3;
        qs[idx]        = row[d];
        ks[n * 33 + d] = row[384 + d];
        vs[idx]        = row[768 + d];
    }
    __syncthreads();

    const float scale = 0.17677669529663687f;
    const float* mrow = mask + (size_t)(b & 63) * 2401;
    for (int idx = tid; idx < 2401; idx += 256) {
        int n = idx / 49, m = idx - n * 49;
        const float* qn = qs + n * 32;
        const float* km = ks + m * 33;
        float s = 0.0f;
        #pragma unroll
        for (int d = 0; d < 32; d++) s += qn[d] * km[d];
        int r1 = n / 7, c1 = n - r1 * 7;
        int r2 = m / 7, c2 = m - r2 * 7;
        int ridx = (r1 - r2 + 6) * 13 + (c1 - c2 + 6);
        sc[idx] = s * scale + rpb[ridx * NHEAD + h] + mrow[idx];
    }
    __syncthreads();

    const int warp = tid >> 5, lane = tid & 31;
    for (int row = warp; row < 49; row += 8) {
        float* sr = sc + row * 49;
        float v0 = sr[lane];
        float v1 = (lane + 32 < 49) ? sr[lane + 32] : -1e30f;
        float mx = fmaxf(v0, v1);
        #pragma unroll
        for (int o2 = 16; o2 > 0; o2 >>= 1) mx = fmaxf(mx, __shfl_xor_sync(FULLMASK, mx, o2));
        float e0 = __expf(v0 - mx);
        float e1 = (lane + 32 < 49) ? __expf(v1 - mx) : 0.0f;
        float sm = e0 + e1;
        #pragma unroll
        for (int o2 = 16; o2 > 0; o2 >>= 1) sm += __shfl_xor_sync(FULLMASK, sm, o2);
        float inv = 1.0f / sm;
        sr[lane] = e0 * inv;
        if (lane + 32 < 49) sr[lane + 32] = e1 * inv;
    }
    __syncthreads();

    for (int idx = tid; idx < 49 * 32; idx += 256) {
        int n = idx >> 5, d = idx & 31;
        const float* pr = sc + n * 49;
        float s = 0.0f;
        #pragma unroll 7
        for (int m = 0; m < 49; m++) s += pr[m] * vs[m * 32 + d];
        o[(size_t)(b * 49 + n) * CDIM + h * HD + d] = __float2half_rn(s);
    }
}

// ---------------- HMMA GEMM: C = A(M,K) @ Bt(N,K)^T + bias, fused epi ------
// fp16 single-term. 8 warps (2x4), warp tile 64x32, 3-stage cp.async.
// EPI: 0 = bias -> fp32 (qkv)     1 = bias + GELU -> fp16 (fc1)
//      2 = bias + window-reverse scatter + residual -> fp32 (proj)
//      3 = bias + residual -> fp32 (fc2 -> d_out)
template<int EPI>
__global__ __launch_bounds__(256, 2)
void gemm_tc(const __half* __restrict__ A, const __half* __restrict__ B,
             const float* __restrict__ bias, const float* __restrict__ res,
             float* __restrict__ outf, __half* __restrict__ oh,
             int N, int K)
{
    extern __shared__ __align__(128) char smem[];
    const uint32_t sbase = smem_u32(smem);
    const int tid  = threadIdx.x;
    const int wid  = tid >> 5, lane = tid & 31;
    const int warp_m = wid & 1, warp_n = wid >> 1;
    const int m0 = blockIdx.y << 7, n0 = blockIdx.x << 7;
    const int nc = K >> 6;

    float acc[4][4][4];
    #pragma unroll
    for (int i = 0; i < 4; i++)
        #pragma unroll
        for (int j = 0; j < 4; j++)
            #pragma unroll
            for (int e = 0; e < 4; e++) acc[i][j][e] = 0.0f;

    auto load_chunk = [&](int k0, int st) {
        const uint32_t so = sbase + st * STAGEB;
        #pragma unroll
        for (int t = 0; t < 2; t++) {
            const __half* gb = t ? B : A;
            const int rb = t ? n0 : m0;
            #pragma unroll
            for (int it = 0; it < 4; it++) {
                int slot = (it << 8) + tid;           // 0..1023
                int row = slot >> 3, seg = slot & 7;
                cp16(so + t * TBYTES + row * ROWB + (seg << 4),
                     gb + (size_t)(rb + row) * K + k0 + (seg << 3));
            }
        }
        CP_COMMIT();
    };

    load_chunk(0, 0);
    load_chunk(BK, 1);                     // nc >= 6 for every call site

    const int arow = (lane & 7) + (lane & 8);
    const int acol = ((lane >> 4) << 3);
    const int brow = (lane & 7) + ((lane >> 1) & 8);
    const int bcol = (lane & 8);

    for (int c = 0; c < nc; c++) {
        if (c + 1 < nc) { CP_WAIT(1); } else { CP_WAIT(0); }
        __syncthreads();

        const uint32_t sA = sbase + (c % NSTAGE) * STAGEB;
        const uint32_t sB = sA + TBYTES;

        #pragma unroll
        for (int ks = 0; ks < 4; ks++) {
            const int kb = ks << 4;
            uint32_t af[4][4];
            #pragma unroll
            for (int mf = 0; mf < 4; mf++)
                ldm_x4(af[mf], sA + (warp_m * 64 + mf * 16 + arow) * ROWB + (kb + acol) * 2);
            uint32_t bf[2][4];
            #pragma unroll
            for (int nt = 0; nt < 2; nt++)
                ldm_x4(bf[nt], sB + (warp_n * 32 + nt * 16 + brow) * ROWB + (kb + bcol) * 2);
            #pragma unroll
            for (int mf = 0; mf < 4; mf++)
                #pragma unroll
                for (int nf = 0; nf < 4; nf++) {
                    const int nt = nf >> 1, bs = (nf & 1) << 1;
                    mma_f16(acc[mf][nf], af[mf], bf[nt][bs], bf[nt][bs + 1]);
                }
        }
        __syncthreads();
        if (c + 2 < nc) load_chunk((c + 2) << 6, (c + 2) % NSTAGE);
    }

    // ---------------- epilogue ---------------------------------------------
    #pragma unroll
    for (int mf = 0; mf < 4; mf++) {
        #pragma unroll
        for (int hh = 0; hh < 2; hh++) {
            const int gm = m0 + warp_m * 64 + mf * 16 + (lane >> 2) + hh * 8;
            size_t obase;
            if (EPI == 2) {
                int bwin  = gm / 49;
                int n     = gm - bwin * 49;
                int batch = bwin >> 6;
                int widx  = bwin & 63;
                int wh = widx >> 3, ww = widx & 7;
                int r = n / 7, cc = n - r * 7;
                int fr = wh * 7 + r + 3;  if (fr >= 56) fr -= 56;
                int fc = ww * 7 + cc + 3; if (fc >= 56) fc -= 56;
                obase = ((size_t)batch * 3136 + fr * 56 + fc) * CDIM;
            } else {
                obase = (size_t)gm * N;
            }
            #pragma unroll
            for (int nf = 0; nf < 4; nf++) {
                const int gn = n0 + warp_n * 32 + nf * 8 + ((lane & 3) << 1);
                float v0 = acc[mf][nf][hh * 2 + 0];
                float v1 = acc[mf][nf][hh * 2 + 1];
                float2 bv = *(const float2*)(bias + gn);
                v0 += bv.x; v1 += bv.y;
                if (EPI == 1) {
                    v0 = 0.5f * v0 * (1.0f + erff(v0 * 0.70710678118654752f));
                    v1 = 0.5f * v1 * (1.0f + erff(v1 * 0.70710678118654752f));
                    __half2 hp;
                    hp.x = __float2half_rn(v0); hp.y = __float2half_rn(v1);
                    *(__half2*)(oh + obase + gn) = hp;
                } else {
                    if (EPI == 2 || EPI == 3) {
                        float2 rv = *(const float2*)(res + obase + gn);
                        v0 += rv.x; v1 += rv.y;
                    }
                    float2 o; o.x = v0; o.y = v1;
                    *(float2*)(outf + obase + gn) = o;
                }
            }
        }
    }
}

// ---------------------------------------------------------------------------
extern "C" void kernel_launch(void* const* d_in, const int* in_sizes, int n_in,
                              void* d_out, int out_size)
{
    const float* x     = (const float*)d_in[0];
    const float* amask = (const float*)d_in[1];
    const float* n1g   = (const float*)d_in[2];
    const float* n1b   = (const float*)d_in[3];
    const float* qkvW  = (const float*)d_in[4];
    const float* qkvB  = (const float*)d_in[5];
    const float* rpb   = (const float*)d_in[6];
    const float* projW = (const float*)d_in[7];
    const float* projB = (const float*)d_in[8];
    const float* n2g   = (const float*)d_in[9];
    const float* n2b   = (const float*)d_in[10];
    const float* fc1W  = (const float*)d_in[11];
    const float* fc1B  = (const float*)d_in[12];
    const float* fc2W  = (const float*)d_in[13];
    const float* fc2B  = (const float*)d_in[14];
    float* out = (float*)d_out;

    float *qkv, *x1;
    __half *a16, *h16, *wq, *wp, *w1, *w2;
    cudaGetSymbolAddress((void**)&qkv, g_qkv);
    cudaGetSymbolAddress((void**)&x1,  g_x1);
    cudaGetSymbolAddress((void**)&a16, g_a);
    cudaGetSymbolAddress((void**)&h16, g_h);
    cudaGetSymbolAddress((void**)&wq,  g_wqkv);
    cudaGetSymbolAddress((void**)&wp,  g_wprj);
    cudaGetSymbolAddress((void**)&w1,  g_wfc1);
    cudaGetSymbolAddress((void**)&w2,  g_wfc2);

    cudaFuncSetAttribute(gemm_tc<0>, cudaFuncAttributeMaxDynamicSharedMemorySize, SMEM_TOTAL);
    cudaFuncSetAttribute(gemm_tc<1>, cudaFuncAttributeMaxDynamicSharedMemorySize, SMEM_TOTAL);
    cudaFuncSetAttribute(gemm_tc<2>, cudaFuncAttributeMaxDynamicSharedMemorySize, SMEM_TOTAL);
    cudaFuncSetAttribute(gemm_tc<3>, cudaFuncAttributeMaxDynamicSharedMemorySize, SMEM_TOTAL);

    // 0. weight transpose to fp16 (tiny)
    wT<<<(N3  * CDIM + 255) / 256, 256>>>(qkvW, wq, CDIM, N3);
    wT<<<(CDIM* CDIM + 255) / 256, 256>>>(projW, wp, CDIM, CDIM);
    wT<<<(HIDD* CDIM + 255) / 256, 256>>>(fc1W, w1, CDIM, HIDD);
    wT<<<(CDIM* HIDD + 255) / 256, 256>>>(fc2W, w2, HIDD, CDIM);

    // 1. LN1 + roll + window partition -> fp16
    ln_kernel<true><<<NTOK, 128>>>(x, n1g, n1b, a16);
    // 2. qkv GEMM (N=1152, K=384) -> fp32
    gemm_tc<0><<<dim3(9, 784), 256, SMEM_TOTAL>>>(a16, wq, qkvB, nullptr, qkv, nullptr, N3, CDIM);
    // 3. windowed attention -> fp16 (reuse a16)
    attn_kernel<<<dim3(NHEAD, 2048), 256>>>(qkv, rpb, amask, a16);
    // 4. proj GEMM + window-reverse scatter + residual(x) -> x1
    gemm_tc<2><<<dim3(3, 784), 256, SMEM_TOTAL>>>(a16, wp, projB, x, x1, nullptr, CDIM, CDIM);
    // 5. LN2 -> fp16
    ln_kernel<false><<<NTOK, 128>>>(x1, n2g, n2b, a16);
    // 6. fc1 GEMM + GELU -> fp16 hidden
    gemm_tc<1><<<dim3(12, 784), 256, SMEM_TOTAL>>>(a16, w1, fc1B, nullptr, nullptr, h16, HIDD, CDIM);
    // 7. fc2 GEMM + residual(x1) -> d_out
    gemm_tc<3><<<dim3(3, 784), 256, SMEM_TOTAL>>>(h16, w2, fc2B, x1, out, nullptr, CDIM, HIDD);
}

// round 13
// speedup vs baseline: 4.0739x; 1.1197x over previous
#include <cuda_runtime.h>
#include <cuda_fp16.h>
#include <math.h>
#include <stdint.h>

// ---------------------------------------------------------------------------
// SwinBlock, GEMMs on HMMA mma.sync m16n8k16 fp16 (fp32 acc).
// qkv stored fp16; attention kernel restructured for ~2.6x less smem traffic
// (q in registers + broadcast, float4 k reads, float2 v reads, 2 rows/warp).
// Shapes fixed: B=32, H=W=56, C=384, NH=12, hd=32, WS=7, SHIFT=3, HID=1536
// ---------------------------------------------------------------------------

#define NTOK   100352          // 2048 windows * 49 tokens
#define CDIM   384
#define NHEAD  12
#define HD     32
#define N3     1152
#define HIDD   1536
#define FULLMASK 0xffffffffu

// GEMM tiling: CTA 128x128, BK=64, 3-stage cp.async pipeline
#define BK       64
#define ROWB     144                       // 64 fp16 = 128B, padded to 144B
#define TBYTES   (128 * ROWB)              // 18432 per tensor tile
#define STAGEB   (2 * TBYTES)              // A tile + B tile = 36864
#define NSTAGE   3
#define SMEM_TOTAL (NSTAGE * STAGEB)       // 110592 B dynamic smem

// ---------------- scratch (static device globals; no allocation) -----------
__device__ __half  g_qkv16[(size_t)NTOK * N3];  // fp16 qkv
__device__ float   g_x1 [(size_t)NTOK * CDIM];  // residual stream
__device__ __half  g_a  [(size_t)NTOK * CDIM];  // fp16 activations (reused)
__device__ __half  g_h  [(size_t)NTOK * HIDD];  // fp16 MLP hidden
// transposed fp16 weights: Wt[N][K]
__device__ __half  g_wqkv[N3  * CDIM];
__device__ __half  g_wprj[CDIM* CDIM];
__device__ __half  g_wfc1[HIDD* CDIM];
__device__ __half  g_wfc2[CDIM* HIDD];

// ---------------- PTX helpers ----------------------------------------------
__device__ __forceinline__ uint32_t smem_u32(const void* p) {
    uint32_t a;
    asm("{ .reg .u64 t; cvta.to.shared.u64 t, %1; cvt.u32.u64 %0, t; }"
        : "=r"(a) : "l"(p));
    return a;
}
__device__ __forceinline__ void ldm_x4(uint32_t* r, uint32_t a) {
    asm volatile("ldmatrix.sync.aligned.m8n8.x4.shared.b16 {%0,%1,%2,%3}, [%4];"
                 : "=r"(r[0]), "=r"(r[1]), "=r"(r[2]), "=r"(r[3]) : "r"(a));
}
__device__ __forceinline__ void mma_f16(float* c, const uint32_t* a,
                                        uint32_t b0, uint32_t b1) {
    asm volatile("mma.sync.aligned.m16n8k16.row.col.f32.f16.f16.f32 "
                 "{%0,%1,%2,%3}, {%4,%5,%6,%7}, {%8,%9}, {%0,%1,%2,%3};"
                 : "+f"(c[0]), "+f"(c[1]), "+f"(c[2]), "+f"(c[3])
                 : "r"(a[0]), "r"(a[1]), "r"(a[2]), "r"(a[3]), "r"(b0), "r"(b1));
}
__device__ __forceinline__ void cp16(uint32_t sa, const void* ga) {
    asm volatile("cp.async.cg.shared.global [%0], [%1], 16;" :: "r"(sa), "l"(ga));
}
#define CP_COMMIT()  asm volatile("cp.async.commit_group;")
#define CP_WAIT(n)   asm volatile("cp.async.wait_group %0;" :: "n"(n))

// ---------------- weight transpose to fp16: W[K][N] -> Wt[N][K] -------------
__global__ void wT(const float* __restrict__ W, __half* __restrict__ o, int K, int N)
{
    int idx = blockIdx.x * 256 + threadIdx.x;
    if (idx >= K * N) return;
    int n = idx / K, k = idx - n * K;
    o[idx] = __float2half_rn(W[(size_t)k * N + n]);
}

// ---------------- LayerNorm (optionally fused roll + window partition) -----
template<bool WINDOW>
__global__ __launch_bounds__(128)
void ln_kernel(const float* __restrict__ x, const float* __restrict__ g,
               const float* __restrict__ bta, __half* __restrict__ o)
{
    __shared__ float sa[4], sb[4];
    const int token = blockIdx.x;
    size_t src;
    if (WINDOW) {
        int bwin  = token / 49;
        int n     = token - bwin * 49;
        int batch = bwin >> 6;
        int widx  = bwin & 63;
        int wh = widx >> 3, ww = widx & 7;
        int r = n / 7, c = n - r * 7;
        int fr = wh * 7 + r + 3; if (fr >= 56) fr -= 56;
        int fc = ww * 7 + c + 3; if (fc >= 56) fc -= 56;
        src = (size_t)batch * 3136 + fr * 56 + fc;
    } else {
        src = token;
    }
    const float* xr = x + src * CDIM;
    const int tid = threadIdx.x;
    float v0 = xr[tid], v1 = xr[tid + 128], v2 = xr[tid + 256];
    float s  = v0 + v1 + v2;
    float s2 = v0 * v0 + v1 * v1 + v2 * v2;
    #pragma unroll
    for (int o2 = 16; o2 > 0; o2 >>= 1) {
        s  += __shfl_xor_sync(FULLMASK, s,  o2);
        s2 += __shfl_xor_sync(FULLMASK, s2, o2);
    }
    int w = tid >> 5;
    if ((tid & 31) == 0) { sa[w] = s; sb[w] = s2; }
    __syncthreads();
    s  = sa[0] + sa[1] + sa[2] + sa[3];
    s2 = sb[0] + sb[1] + sb[2] + sb[3];
    const float mean = s * (1.0f / 384.0f);
    const float var  = s2 * (1.0f / 384.0f) - mean * mean;
    const float rstd = rsqrtf(var + 1e-5f);
    size_t ob = (size_t)token * CDIM;
    o[ob + tid]       = __float2half_rn((v0 - mean) * rstd * g[tid]       + bta[tid]);
    o[ob + tid + 128] = __float2half_rn((v1 - mean) * rstd * g[tid + 128] + bta[tid + 128]);
    o[ob + tid + 256] = __float2half_rn((v2 - mean) * rstd * g[tid + 256] + bta[tid + 256]);
}

// ---------------- windowed attention: one block per (window, head) ---------
// Smem-traffic-optimized: scores = warp-per-row (q in regs, broadcast loads,
// float4 k reads at 144B stride -> conflict-free); PV = 2 rows per warp with
// float2 v reads. qkv read as fp16.
__global__ __launch_bounds__(256)
void attn_kernel(const __half* __restrict__ qkv, const float* __restrict__ rpb,
                 const float* __restrict__ mask, __half* __restrict__ o)
{
    __shared__ float qs[49 * 36];   // 144B row stride
    __shared__ float ks[49 * 36];
    __shared__ float vs[49 * 32];
    __shared__ float sc[49 * 49];

    const int b = blockIdx.y;
    const int h = blockIdx.x;
    const int tid = threadIdx.x;
    const int warp = tid >> 5, lane = tid & 31;

    const __half* base = qkv + (size_t)b * 49 * N3 + h * HD;
    for (int idx = tid; idx < 49 * 16; idx += 256) {
        int n = idx >> 4, d2 = idx & 15;
        const __half2* row = (const __half2*)(base + (size_t)n * N3);
        float2 q2 = __half22float2(row[d2]);
        float2 k2 = __half22float2(row[192 + d2]);   // +384 halves
        float2 v2 = __half22float2(row[384 + d2]);   // +768 halves
        qs[n * 36 + 2 * d2] = q2.x; qs[n * 36 + 2 * d2 + 1] = q2.y;
        ks[n * 36 + 2 * d2] = k2.x; ks[n * 36 + 2 * d2 + 1] = k2.y;
        vs[n * 32 + 2 * d2] = v2.x; vs[n * 32 + 2 * d2 + 1] = v2.y;
    }
    __syncthreads();

    const float scale = 0.17677669529663687f;  // 1/sqrt(32)
    const float* mrow = mask + (size_t)(b & 63) * 2401;

    // ---- scores: warp w handles rows {w, w+8, ...}; lane covers m=lane,(lane+32)
    for (int n = warp; n < 49; n += 8) {
        float4 q[8];
        #pragma unroll
        for (int s = 0; s < 8; s++) q[s] = *(const float4*)&qs[n * 36 + s * 4];
        const int r1 = n / 7, c1 = n - r1 * 7;

        float s0 = 0.0f;
        #pragma unroll
        for (int s = 0; s < 8; s++) {
            float4 k0 = *(const float4*)&ks[lane * 36 + s * 4];
            s0 += q[s].x * k0.x + q[s].y * k0.y + q[s].z * k0.z + q[s].w * k0.w;
        }
        float s1 = 0.0f;
        if (lane < 17) {
            #pragma unroll
            for (int s = 0; s < 8; s++) {
                float4 k1 = *(const float4*)&ks[(lane + 32) * 36 + s * 4];
                s1 += q[s].x * k1.x + q[s].y * k1.y + q[s].z * k1.z + q[s].w * k1.w;
            }
        }
        {
            const int m = lane;
            int r2 = m / 7, c2 = m - r2 * 7;
            int ridx = (r1 - r2 + 6) * 13 + (c1 - c2 + 6);
            sc[n * 49 + m] = s0 * scale + rpb[ridx * NHEAD + h] + mrow[n * 49 + m];
        }
        if (lane < 17) {
            const int m = lane + 32;
            int r2 = m / 7, c2 = m - r2 * 7;
            int ridx = (r1 - r2 + 6) * 13 + (c1 - c2 + 6);
            sc[n * 49 + m] = s1 * scale + rpb[ridx * NHEAD + h] + mrow[n * 49 + m];
        }
    }
    __syncthreads();

    // ---- softmax: warp per row
    for (int row = warp; row < 49; row += 8) {
        float* sr = sc + row * 49;
        float v0 = sr[lane];
        float v1 = (lane + 32 < 49) ? sr[lane + 32] : -1e30f;
        float mx = fmaxf(v0, v1);
        #pragma unroll
        for (int o2 = 16; o2 > 0; o2 >>= 1) mx = fmaxf(mx, __shfl_xor_sync(FULLMASK, mx, o2));
        float e0 = __expf(v0 - mx);
        float e1 = (lane + 32 < 49) ? __expf(v1 - mx) : 0.0f;
        float sm = e0 + e1;
        #pragma unroll
        for (int o2 = 16; o2 > 0; o2 >>= 1) sm += __shfl_xor_sync(FULLMASK, sm, o2);
        float inv = 1.0f / sm;
        sr[lane] = e0 * inv;
        if (lane + 32 < 49) sr[lane + 32] = e1 * inv;
    }
    __syncthreads();

    // ---- PV: warp handles 2 rows at a time; lane = (row-half, d-pair)
    const int half_ = lane >> 4, d2 = lane & 15;
    for (int np = warp; np < 25; np += 8) {
        const int n = np * 2 + half_;
        if (n < 49) {
            const float* pr = sc + n * 49;
            float ax = 0.0f, ay = 0.0f;
            #pragma unroll 7
            for (int m = 0; m < 49; m++) {
                float p = pr[m];
                float2 vv = *(const float2*)&vs[m * 32 + 2 * d2];
                ax += p * vv.x; ay += p * vv.y;
            }
            __half2 hp;
            hp.x = __float2half_rn(ax); hp.y = __float2half_rn(ay);
            *(__half2*)(o + (size_t)(b * 49 + n) * CDIM + h * HD + 2 * d2) = hp;
        }
    }
}

// ---------------- HMMA GEMM: C = A(M,K) @ Bt(N,K)^T + bias, fused epi ------
// fp16 single-term. 8 warps (2x4), warp tile 64x32, 3-stage cp.async.
// EPI: 0 = bias -> fp16 (qkv)     1 = bias + GELU -> fp16 (fc1)
//      2 = bias + window-reverse scatter + residual -> fp32 (proj)
//      3 = bias + residual -> fp32 (fc2 -> d_out)
template<int EPI>
__global__ __launch_bounds__(256, 2)
void gemm_tc(const __half* __restrict__ A, const __half* __restrict__ B,
             const float* __restrict__ bias, const float* __restrict__ res,
             float* __restrict__ outf, __half* __restrict__ oh,
             int N, int K)
{
    extern __shared__ __align__(128) char smem[];
    const uint32_t sbase = smem_u32(smem);
    const int tid  = threadIdx.x;
    const int wid  = tid >> 5, lane = tid & 31;
    const int warp_m = wid & 1, warp_n = wid >> 1;
    const int m0 = blockIdx.y << 7, n0 = blockIdx.x << 7;
    const int nc = K >> 6;

    float acc[4][4][4];
    #pragma unroll
    for (int i = 0; i < 4; i++)
        #pragma unroll
        for (int j = 0; j < 4; j++)
            #pragma unroll
            for (int e = 0; e < 4; e++) acc[i][j][e] = 0.0f;

    auto load_chunk = [&](int k0, int st) {
        const uint32_t so = sbase + st * STAGEB;
        #pragma unroll
        for (int t = 0; t < 2; t++) {
            const __half* gb = t ? B : A;
            const int rb = t ? n0 : m0;
            #pragma unroll
            for (int it = 0; it < 4; it++) {
                int slot = (it << 8) + tid;           // 0..1023
                int row = slot >> 3, seg = slot & 7;
                cp16(so + t * TBYTES + row * ROWB + (seg << 4),
                     gb + (size_t)(rb + row) * K + k0 + (seg << 3));
            }
        }
        CP_COMMIT();
    };

    load_chunk(0, 0);
    load_chunk(BK, 1);                     // nc >= 6 for every call site

    const int arow = (lane & 7) + (lane & 8);
    const int acol = ((lane >> 4) << 3);
    const int brow = (lane & 7) + ((lane >> 1) & 8);
    const int bcol = (lane & 8);

    for (int c = 0; c < nc; c++) {
        if (c + 1 < nc) { CP_WAIT(1); } else { CP_WAIT(0); }
        __syncthreads();

        const uint32_t sA = sbase + (c % NSTAGE) * STAGEB;
        const uint32_t sB = sA + TBYTES;

        #pragma unroll
        for (int ks = 0; ks < 4; ks++) {
            const int kb = ks << 4;
            uint32_t af[4][4];
            #pragma unroll
            for (int mf = 0; mf < 4; mf++)
                ldm_x4(af[mf], sA + (warp_m * 64 + mf * 16 + arow) * ROWB + (kb + acol) * 2);
            uint32_t bf[2][4];
            #pragma unroll
            for (int nt = 0; nt < 2; nt++)
                ldm_x4(bf[nt], sB + (warp_n * 32 + nt * 16 + brow) * ROWB + (kb + bcol) * 2);
            #pragma unroll
            for (int mf = 0; mf < 4; mf++)
                #pragma unroll
                for (int nf = 0; nf < 4; nf++) {
                    const int nt = nf >> 1, bs = (nf & 1) << 1;
                    mma_f16(acc[mf][nf], af[mf], bf[nt][bs], bf[nt][bs + 1]);
                }
        }
        __syncthreads();
        if (c + 2 < nc) load_chunk((c + 2) << 6, (c + 2) % NSTAGE);
    }

    // ---------------- epilogue ---------------------------------------------
    #pragma unroll
    for (int mf = 0; mf < 4; mf++) {
        #pragma unroll
        for (int hh = 0; hh < 2; hh++) {
            const int gm = m0 + warp_m * 64 + mf * 16 + (lane >> 2) + hh * 8;
            size_t obase;
            if (EPI == 2) {
                int bwin  = gm / 49;
                int n     = gm - bwin * 49;
                int batch = bwin >> 6;
                int widx  = bwin & 63;
                int wh = widx >> 3, ww = widx & 7;
                int r = n / 7, cc = n - r * 7;
                int fr = wh * 7 + r + 3;  if (fr >= 56) fr -= 56;
                int fc = ww * 7 + cc + 3; if (fc >= 56) fc -= 56;
                obase = ((size_t)batch * 3136 + fr * 56 + fc) * CDIM;
            } else {
                obase = (size_t)gm * N;
            }
            #pragma unroll
            for (int nf = 0; nf < 4; nf++) {
                const int gn = n0 + warp_n * 32 + nf * 8 + ((lane & 3) << 1);
                float v0 = acc[mf][nf][hh * 2 + 0];
                float v1 = acc[mf][nf][hh * 2 + 1];
                float2 bv = *(const float2*)(bias + gn);
                v0 += bv.x; v1 += bv.y;
                if (EPI == 0 || EPI == 1) {
                    if (EPI == 1) {
                        v0 = 0.5f * v0 * (1.0f + erff(v0 * 0.70710678118654752f));
                        v1 = 0.5f * v1 * (1.0f + erff(v1 * 0.70710678118654752f));
                    }
                    __half2 hp;
                    hp.x = __float2half_rn(v0); hp.y = __float2half_rn(v1);
                    *(__half2*)(oh + obase + gn) = hp;
                } else {
                    float2 rv = *(const float2*)(res + obase + gn);
                    v0 += rv.x; v1 += rv.y;
                    float2 o; o.x = v0; o.y = v1;
                    *(float2*)(outf + obase + gn) = o;
                }
            }
        }
    }
}

// ---------------------------------------------------------------------------
extern "C" void kernel_launch(void* const* d_in, const int* in_sizes, int n_in,
                              void* d_out, int out_size)
{
    const float* x     = (const float*)d_in[0];
    const float* amask = (const float*)d_in[1];
    const float* n1g   = (const float*)d_in[2];
    const float* n1b   = (const float*)d_in[3];
    const float* qkvW  = (const float*)d_in[4];
    const float* qkvB  = (const float*)d_in[5];
    const float* rpb   = (const float*)d_in[6];
    const float* projW = (const float*)d_in[7];
    const float* projB = (const float*)d_in[8];
    const float* n2g   = (const float*)d_in[9];
    const float* n2b   = (const float*)d_in[10];
    const float* fc1W  = (const float*)d_in[11];
    const float* fc1B  = (const float*)d_in[12];
    const float* fc2W  = (const float*)d_in[13];
    const float* fc2B  = (const float*)d_in[14];
    float* out = (float*)d_out;

    float *x1;
    __half *qkv16, *a16, *h16, *wq, *wp, *w1, *w2;
    cudaGetSymbolAddress((void**)&qkv16, g_qkv16);
    cudaGetSymbolAddress((void**)&x1,  g_x1);
    cudaGetSymbolAddress((void**)&a16, g_a);
    cudaGetSymbolAddress((void**)&h16, g_h);
    cudaGetSymbolAddress((void**)&wq,  g_wqkv);
    cudaGetSymbolAddress((void**)&wp,  g_wprj);
    cudaGetSymbolAddress((void**)&w1,  g_wfc1);
    cudaGetSymbolAddress((void**)&w2,  g_wfc2);

    cudaFuncSetAttribute(gemm_tc<0>, cudaFuncAttributeMaxDynamicSharedMemorySize, SMEM_TOTAL);
    cudaFuncSetAttribute(gemm_tc<1>, cudaFuncAttributeMaxDynamicSharedMemorySize, SMEM_TOTAL);
    cudaFuncSetAttribute(gemm_tc<2>, cudaFuncAttributeMaxDynamicSharedMemorySize, SMEM_TOTAL);
    cudaFuncSetAttribute(gemm_tc<3>, cudaFuncAttributeMaxDynamicSharedMemorySize, SMEM_TOTAL);

    // 0. weight transpose to fp16 (tiny)
    wT<<<(N3  * CDIM + 255) / 256, 256>>>(qkvW, wq, CDIM, N3);
    wT<<<(CDIM* CDIM + 255) / 256, 256>>>(projW, wp, CDIM, CDIM);
    wT<<<(HIDD* CDIM + 255) / 256, 256>>>(fc1W, w1, CDIM, HIDD);
    wT<<<(CDIM* HIDD + 255) / 256, 256>>>(fc2W, w2, HIDD, CDIM);

    // 1. LN1 + roll + window partition -> fp16
    ln_kernel<true><<<NTOK, 128>>>(x, n1g, n1b, a16);
    // 2. qkv GEMM (N=1152, K=384) -> fp16
    gemm_tc<0><<<dim3(9, 784), 256, SMEM_TOTAL>>>(a16, wq, qkvB, nullptr, nullptr, qkv16, N3, CDIM);
    // 3. windowed attention -> fp16 (reuse a16)
    attn_kernel<<<dim3(NHEAD, 2048), 256>>>(qkv16, rpb, amask, a16);
    // 4. proj GEMM + window-reverse scatter + residual(x) -> x1
    gemm_tc<2><<<dim3(3, 784), 256, SMEM_TOTAL>>>(a16, wp, projB, x, x1, nullptr, CDIM, CDIM);
    // 5. LN2 -> fp16
    ln_kernel<false><<<NTOK, 128>>>(x1, n2g, n2b, a16);
    // 6. fc1 GEMM + GELU -> fp16 hidden
    gemm_tc<1><<<dim3(12, 784), 256, SMEM_TOTAL>>>(a16, w1, fc1B, nullptr, nullptr, h16, HIDD, CDIM);
    // 7. fc2 GEMM + residual(x1) -> d_out
    gemm_tc<3><<<dim3(3, 784), 256, SMEM_TOTAL>>>(h16, w2, fc2B, x1, out, nullptr, CDIM, HIDD);
}

// round 14
// speedup vs baseline: 4.1363x; 1.0153x over previous
#include <cuda_runtime.h>
#include <cuda_fp16.h>
#include <math.h>
#include <stdint.h>

// ---------------------------------------------------------------------------
// SwinBlock, GEMMs on HMMA mma.sync m16n8k16 fp16 (fp32 acc).
// Warp tile 64x64 (4 warps/CTA, 2 CTAs/SM), 2-stage cp.async pipeline.
// Shapes fixed: B=32, H=W=56, C=384, NH=12, hd=32, WS=7, SHIFT=3, HID=1536
// ---------------------------------------------------------------------------

#define NTOK   100352          // 2048 windows * 49 tokens
#define CDIM   384
#define NHEAD  12
#define HD     32
#define N3     1152
#define HIDD   1536
#define FULLMASK 0xffffffffu

// GEMM tiling: CTA 128x128, BK=64, 2-stage cp.async pipeline, 128 threads
#define BK       64
#define ROWB     144                       // 64 fp16 = 128B, padded to 144B
#define TBYTES   (128 * ROWB)              // 18432 per tensor tile
#define STAGEB   (2 * TBYTES)              // A tile + B tile = 36864
#define NSTAGE   2
#define SMEM_TOTAL (NSTAGE * STAGEB)       // 73728 B dynamic smem

// ---------------- scratch (static device globals; no allocation) -----------
__device__ __half  g_qkv16[(size_t)NTOK * N3];  // fp16 qkv
__device__ float   g_x1 [(size_t)NTOK * CDIM];  // residual stream
__device__ __half  g_a  [(size_t)NTOK * CDIM];  // fp16 activations (reused)
__device__ __half  g_h  [(size_t)NTOK * HIDD];  // fp16 MLP hidden
// transposed fp16 weights: Wt[N][K]
__device__ __half  g_wqkv[N3  * CDIM];
__device__ __half  g_wprj[CDIM* CDIM];
__device__ __half  g_wfc1[HIDD* CDIM];
__device__ __half  g_wfc2[CDIM* HIDD];

// ---------------- PTX helpers ----------------------------------------------
__device__ __forceinline__ uint32_t smem_u32(const void* p) {
    uint32_t a;
    asm("{ .reg .u64 t; cvta.to.shared.u64 t, %1; cvt.u32.u64 %0, t; }"
        : "=r"(a) : "l"(p));
    return a;
}
__device__ __forceinline__ void ldm_x4(uint32_t* r, uint32_t a) {
    asm volatile("ldmatrix.sync.aligned.m8n8.x4.shared.b16 {%0,%1,%2,%3}, [%4];"
                 : "=r"(r[0]), "=r"(r[1]), "=r"(r[2]), "=r"(r[3]) : "r"(a));
}
__device__ __forceinline__ void mma_f16(float* c, const uint32_t* a,
                                        uint32_t b0, uint32_t b1) {
    asm volatile("mma.sync.aligned.m16n8k16.row.col.f32.f16.f16.f32 "
                 "{%0,%1,%2,%3}, {%4,%5,%6,%7}, {%8,%9}, {%0,%1,%2,%3};"
                 : "+f"(c[0]), "+f"(c[1]), "+f"(c[2]), "+f"(c[3])
                 : "r"(a[0]), "r"(a[1]), "r"(a[2]), "r"(a[3]), "r"(b0), "r"(b1));
}
__device__ __forceinline__ void cp16(uint32_t sa, const void* ga) {
    asm volatile("cp.async.cg.shared.global [%0], [%1], 16;" :: "r"(sa), "l"(ga));
}
#define CP_COMMIT()  asm volatile("cp.async.commit_group;")
#define CP_WAIT(n)   asm volatile("cp.async.wait_group %0;" :: "n"(n))

// ---------------- weight transpose to fp16: W[K][N] -> Wt[N][K] -------------
__global__ void wT(const float* __restrict__ W, __half* __restrict__ o, int K, int N)
{
    int idx = blockIdx.x * 256 + threadIdx.x;
    if (idx >= K * N) return;
    int n = idx / K, k = idx - n * K;
    o[idx] = __float2half_rn(W[(size_t)k * N + n]);
}

// ---------------- LayerNorm (optionally fused roll + window partition) -----
template<bool WINDOW>
__global__ __launch_bounds__(128)
void ln_kernel(const float* __restrict__ x, const float* __restrict__ g,
               const float* __restrict__ bta, __half* __restrict__ o)
{
    __shared__ float sa[4], sb[4];
    const int token = blockIdx.x;
    size_t src;
    if (WINDOW) {
        int bwin  = token / 49;
        int n     = token - bwin * 49;
        int batch = bwin >> 6;
        int widx  = bwin & 63;
        int wh = widx >> 3, ww = widx & 7;
        int r = n / 7, c = n - r * 7;
        int fr = wh * 7 + r + 3; if (fr >= 56) fr -= 56;
        int fc = ww * 7 + c + 3; if (fc >= 56) fc -= 56;
        src = (size_t)batch * 3136 + fr * 56 + fc;
    } else {
        src = token;
    }
    const float* xr = x + src * CDIM;
    const int tid = threadIdx.x;
    float v0 = xr[tid], v1 = xr[tid + 128], v2 = xr[tid + 256];
    float s  = v0 + v1 + v2;
    float s2 = v0 * v0 + v1 * v1 + v2 * v2;
    #pragma unroll
    for (int o2 = 16; o2 > 0; o2 >>= 1) {
        s  += __shfl_xor_sync(FULLMASK, s,  o2);
        s2 += __shfl_xor_sync(FULLMASK, s2, o2);
    }
    int w = tid >> 5;
    if ((tid & 31) == 0) { sa[w] = s; sb[w] = s2; }
    __syncthreads();
    s  = sa[0] + sa[1] + sa[2] + sa[3];
    s2 = sb[0] + sb[1] + sb[2] + sb[3];
    const float mean = s * (1.0f / 384.0f);
    const float var  = s2 * (1.0f / 384.0f) - mean * mean;
    const float rstd = rsqrtf(var + 1e-5f);
    size_t ob = (size_t)token * CDIM;
    o[ob + tid]       = __float2half_rn((v0 - mean) * rstd * g[tid]       + bta[tid]);
    o[ob + tid + 128] = __float2half_rn((v1 - mean) * rstd * g[tid + 128] + bta[tid + 128]);
    o[ob + tid + 256] = __float2half_rn((v2 - mean) * rstd * g[tid + 256] + bta[tid + 256]);
}

// ---------------- windowed attention: one block per (window, head) ---------
__global__ __launch_bounds__(256)
void attn_kernel(const __half* __restrict__ qkv, const float* __restrict__ rpb,
                 const float* __restrict__ mask, __half* __restrict__ o)
{
    __shared__ float qs[49 * 36];   // 144B row stride
    __shared__ float ks[49 * 36];
    __shared__ float vs[49 * 32];
    __shared__ float sc[49 * 49];

    const int b = blockIdx.y;
    const int h = blockIdx.x;
    const int tid = threadIdx.x;
    const int warp = tid >> 5, lane = tid & 31;

    const __half* base = qkv + (size_t)b * 49 * N3 + h * HD;
    for (int idx = tid; idx < 49 * 16; idx += 256) {
        int n = idx >> 4, d2 = idx & 15;
        const __half2* row = (const __half2*)(base + (size_t)n * N3);
        float2 q2 = __half22float2(row[d2]);
        float2 k2 = __half22float2(row[192 + d2]);   // +384 halves
        float2 v2 = __half22float2(row[384 + d2]);   // +768 halves
        qs[n * 36 + 2 * d2] = q2.x; qs[n * 36 + 2 * d2 + 1] = q2.y;
        ks[n * 36 + 2 * d2] = k2.x; ks[n * 36 + 2 * d2 + 1] = k2.y;
        vs[n * 32 + 2 * d2] = v2.x; vs[n * 32 + 2 * d2 + 1] = v2.y;
    }
    __syncthreads();

    const float scale = 0.17677669529663687f;  // 1/sqrt(32)
    const float* mrow = mask + (size_t)(b & 63) * 2401;

    // ---- scores: warp w handles rows {w, w+8, ...}; lane covers m=lane,(lane+32)
    for (int n = warp; n < 49; n += 8) {
        float4 q[8];
        #pragma unroll
        for (int s = 0; s < 8; s++) q[s] = *(const float4*)&qs[n * 36 + s * 4];
        const int r1 = n / 7, c1 = n - r1 * 7;

        float s0 = 0.0f;
        #pragma unroll
        for (int s = 0; s < 8; s++) {
            float4 k0 = *(const float4*)&ks[lane * 36 + s * 4];
            s0 += q[s].x * k0.x + q[s].y * k0.y + q[s].z * k0.z + q[s].w * k0.w;
        }
        float s1 = 0.0f;
        if (lane < 17) {
            #pragma unroll
            for (int s = 0; s < 8; s++) {
                float4 k1 = *(const float4*)&ks[(lane + 32) * 36 + s * 4];
                s1 += q[s].x * k1.x + q[s].y * k1.y + q[s].z * k1.z + q[s].w * k1.w;
            }
        }
        {
            const int m = lane;
            int r2 = m / 7, c2 = m - r2 * 7;
            int ridx = (r1 - r2 + 6) * 13 + (c1 - c2 + 6);
            sc[n * 49 + m] = s0 * scale + rpb[ridx * NHEAD + h] + mrow[n * 49 + m];
        }
        if (lane < 17) {
            const int m = lane + 32;
            int r2 = m / 7, c2 = m - r2 * 7;
            int ridx = (r1 - r2 + 6) * 13 + (c1 - c2 + 6);
            sc[n * 49 + m] = s1 * scale + rpb[ridx * NHEAD + h] + mrow[n * 49 + m];
        }
    }
    __syncthreads();

    // ---- softmax: warp per row
    for (int row = warp; row < 49; row += 8) {
        float* sr = sc + row * 49;
        float v0 = sr[lane];
        float v1 = (lane + 32 < 49) ? sr[lane + 32] : -1e30f;
        float mx = fmaxf(v0, v1);
        #pragma unroll
        for (int o2 = 16; o2 > 0; o2 >>= 1) mx = fmaxf(mx, __shfl_xor_sync(FULLMASK, mx, o2));
        float e0 = __expf(v0 - mx);
        float e1 = (lane + 32 < 49) ? __expf(v1 - mx) : 0.0f;
        float sm = e0 + e1;
        #pragma unroll
        for (int o2 = 16; o2 > 0; o2 >>= 1) sm += __shfl_xor_sync(FULLMASK, sm, o2);
        float inv = 1.0f / sm;
        sr[lane] = e0 * inv;
        if (lane + 32 < 49) sr[lane + 32] = e1 * inv;
    }
    __syncthreads();

    // ---- PV: warp handles 2 rows at a time; lane = (row-half, d-pair)
    const int half_ = lane >> 4, d2 = lane & 15;
    for (int np = warp; np < 25; np += 8) {
        const int n = np * 2 + half_;
        if (n < 49) {
            const float* pr = sc + n * 49;
            float ax = 0.0f, ay = 0.0f;
            #pragma unroll 7
            for (int m = 0; m < 49; m++) {
                float p = pr[m];
                float2 vv = *(const float2*)&vs[m * 32 + 2 * d2];
                ax += p * vv.x; ay += p * vv.y;
            }
            __half2 hp;
            hp.x = __float2half_rn(ax); hp.y = __float2half_rn(ay);
            *(__half2*)(o + (size_t)(b * 49 + n) * CDIM + h * HD + 2 * d2) = hp;
        }
    }
}

// ---------------- HMMA GEMM: C = A(M,K) @ Bt(N,K)^T + bias, fused epi ------
// fp16 single-term. 4 warps (2x2), warp tile 64x64, 2-stage cp.async,
// 2 CTAs/SM. Each warp: 8 ldmatrix.x4 per k16 for 32 MMAs.
// EPI: 0 = bias -> fp16 (qkv)     1 = bias + GELU -> fp16 (fc1)
//      2 = bias + window-reverse scatter + residual -> fp32 (proj)
//      3 = bias + residual -> fp32 (fc2 -> d_out)
template<int EPI>
__global__ __launch_bounds__(128, 2)
void gemm_tc(const __half* __restrict__ A, const __half* __restrict__ B,
             const float* __restrict__ bias, const float* __restrict__ res,
             float* __restrict__ outf, __half* __restrict__ oh,
             int N, int K)
{
    extern __shared__ __align__(128) char smem[];
    const uint32_t sbase = smem_u32(smem);
    const int tid  = threadIdx.x;
    const int wid  = tid >> 5, lane = tid & 31;
    const int warp_m = wid & 1, warp_n = wid >> 1;
    const int m0 = blockIdx.y << 7, n0 = blockIdx.x << 7;
    const int nc = K >> 6;

    float acc[4][8][4];
    #pragma unroll
    for (int i = 0; i < 4; i++)
        #pragma unroll
        for (int j = 0; j < 8; j++)
            #pragma unroll
            for (int e = 0; e < 4; e++) acc[i][j][e] = 0.0f;

    auto load_chunk = [&](int k0, int st) {
        const uint32_t so = sbase + st * STAGEB;
        #pragma unroll
        for (int t = 0; t < 2; t++) {
            const __half* gb = t ? B : A;
            const int rb = t ? n0 : m0;
            #pragma unroll
            for (int it = 0; it < 8; it++) {
                int slot = (it << 7) + tid;           // 0..1023
                int row = slot >> 3, seg = slot & 7;
                cp16(so + t * TBYTES + row * ROWB + (seg << 4),
                     gb + (size_t)(rb + row) * K + k0 + (seg << 3));
            }
        }
        CP_COMMIT();
    };

    load_chunk(0, 0);

    const int arow = (lane & 7) + (lane & 8);
    const int acol = ((lane >> 4) << 3);
    const int brow = (lane & 7) + ((lane >> 1) & 8);
    const int bcol = (lane & 8);

    for (int c = 0; c < nc; c++) {
        if (c + 1 < nc) { load_chunk((c + 1) << 6, (c + 1) & 1); CP_WAIT(1); }
        else            { CP_WAIT(0); }
        __syncthreads();

        const uint32_t sA = sbase + (c & 1) * STAGEB;
        const uint32_t sB = sA + TBYTES;

        #pragma unroll
        for (int ks = 0; ks < 4; ks++) {
            const int kb = ks << 4;
            uint32_t af[4][4];
            #pragma unroll
            for (int mf = 0; mf < 4; mf++)
                ldm_x4(af[mf], sA + (warp_m * 64 + mf * 16 + arow) * ROWB + (kb + acol) * 2);
            uint32_t bf[4][4];
            #pragma unroll
            for (int nt = 0; nt < 4; nt++)
                ldm_x4(bf[nt], sB + (warp_n * 64 + nt * 16 + brow) * ROWB + (kb + bcol) * 2);
            #pragma unroll
            for (int mf = 0; mf < 4; mf++)
                #pragma unroll
                for (int nf = 0; nf < 8; nf++) {
                    const int nt = nf >> 1, bs = (nf & 1) << 1;
                    mma_f16(acc[mf][nf], af[mf], bf[nt][bs], bf[nt][bs + 1]);
                }
        }
        __syncthreads();
    }

    // ---------------- epilogue ---------------------------------------------
    #pragma unroll
    for (int mf = 0; mf < 4; mf++) {
        #pragma unroll
        for (int hh = 0; hh < 2; hh++) {
            const int gm = m0 + warp_m * 64 + mf * 16 + (lane >> 2) + hh * 8;
            size_t obase;
            if (EPI == 2) {
                int bwin  = gm / 49;
                int n     = gm - bwin * 49;
                int batch = bwin >> 6;
                int widx  = bwin & 63;
                int wh = widx >> 3, ww = widx & 7;
                int r = n / 7, cc = n - r * 7;
                int fr = wh * 7 + r + 3;  if (fr >= 56) fr -= 56;
                int fc = ww * 7 + cc + 3; if (fc >= 56) fc -= 56;
                obase = ((size_t)batch * 3136 + fr * 56 + fc) * CDIM;
            } else {
                obase = (size_t)gm * N;
            }
            #pragma unroll
            for (int nf = 0; nf < 8; nf++) {
                const int gn = n0 + warp_n * 64 + nf * 8 + ((lane & 3) << 1);
                float v0 = acc[mf][nf][hh * 2 + 0];
                float v1 = acc[mf][nf][hh * 2 + 1];
                float2 bv = *(const float2*)(bias + gn);
                v0 += bv.x; v1 += bv.y;
                if (EPI == 0 || EPI == 1) {
                    if (EPI == 1) {
                        v0 = 0.5f * v0 * (1.0f + erff(v0 * 0.70710678118654752f));
                        v1 = 0.5f * v1 * (1.0f + erff(v1 * 0.70710678118654752f));
                    }
                    __half2 hp;
                    hp.x = __float2half_rn(v0); hp.y = __float2half_rn(v1);
                    *(__half2*)(oh + obase + gn) = hp;
                } else {
                    float2 rv = *(const float2*)(res + obase + gn);
                    v0 += rv.x; v1 += rv.y;
                    float2 o; o.x = v0; o.y = v1;
                    *(float2*)(outf + obase + gn) = o;
                }
            }
        }
    }
}

// ---------------------------------------------------------------------------
extern "C" void kernel_launch(void* const* d_in, const int* in_sizes, int n_in,
                              void* d_out, int out_size)
{
    const float* x     = (const float*)d_in[0];
    const float* amask = (const float*)d_in[1];
    const float* n1g   = (const float*)d_in[2];
    const float* n1b   = (const float*)d_in[3];
    const float* qkvW  = (const float*)d_in[4];
    const float* qkvB  = (const float*)d_in[5];
    const float* rpb   = (const float*)d_in[6];
    const float* projW = (const float*)d_in[7];
    const float* projB = (const float*)d_in[8];
    const float* n2g   = (const float*)d_in[9];
    const float* n2b   = (const float*)d_in[10];
    const float* fc1W  = (const float*)d_in[11];
    const float* fc1B  = (const float*)d_in[12];
    const float* fc2W  = (const float*)d_in[13];
    const float* fc2B  = (const float*)d_in[14];
    float* out = (float*)d_out;

    float *x1;
    __half *qkv16, *a16, *h16, *wq, *wp, *w1, *w2;
    cudaGetSymbolAddress((void**)&qkv16, g_qkv16);
    cudaGetSymbolAddress((void**)&x1,  g_x1);
    cudaGetSymbolAddress((void**)&a16, g_a);
    cudaGetSymbolAddress((void**)&h16, g_h);
    cudaGetSymbolAddress((void**)&wq,  g_wqkv);
    cudaGetSymbolAddress((void**)&wp,  g_wprj);
    cudaGetSymbolAddress((void**)&w1,  g_wfc1);
    cudaGetSymbolAddress((void**)&w2,  g_wfc2);

    cudaFuncSetAttribute(gemm_tc<0>, cudaFuncAttributeMaxDynamicSharedMemorySize, SMEM_TOTAL);
    cudaFuncSetAttribute(gemm_tc<1>, cudaFuncAttributeMaxDynamicSharedMemorySize, SMEM_TOTAL);
    cudaFuncSetAttribute(gemm_tc<2>, cudaFuncAttributeMaxDynamicSharedMemorySize, SMEM_TOTAL);
    cudaFuncSetAttribute(gemm_tc<3>, cudaFuncAttributeMaxDynamicSharedMemorySize, SMEM_TOTAL);

    // 0. weight transpose to fp16 (tiny)
    wT<<<(N3  * CDIM + 255) / 256, 256>>>(qkvW, wq, CDIM, N3);
    wT<<<(CDIM* CDIM + 255) / 256, 256>>>(projW, wp, CDIM, CDIM);
    wT<<<(HIDD* CDIM + 255) / 256, 256>>>(fc1W, w1, CDIM, HIDD);
    wT<<<(CDIM* HIDD + 255) / 256, 256>>>(fc2W, w2, HIDD, CDIM);

    // 1. LN1 + roll + window partition -> fp16
    ln_kernel<true><<<NTOK, 128>>>(x, n1g, n1b, a16);
    // 2. qkv GEMM (N=1152, K=384) -> fp16
    gemm_tc<0><<<dim3(9, 784), 128, SMEM_TOTAL>>>(a16, wq, qkvB, nullptr, nullptr, qkv16, N3, CDIM);
    // 3. windowed attention -> fp16 (reuse a16)
    attn_kernel<<<dim3(NHEAD, 2048), 256>>>(qkv16, rpb, amask, a16);
    // 4. proj GEMM + window-reverse scatter + residual(x) -> x1
    gemm_tc<2><<<dim3(3, 784), 128, SMEM_TOTAL>>>(a16, wp, projB, x, x1, nullptr, CDIM, CDIM);
    // 5. LN2 -> fp16
    ln_kernel<false><<<NTOK, 128>>>(x1, n2g, n2b, a16);
    // 6. fc1 GEMM + GELU -> fp16 hidden
    gemm_tc<1><<<dim3(12, 784), 128, SMEM_TOTAL>>>(a16, w1, fc1B, nullptr, nullptr, h16, HIDD, CDIM);
    // 7. fc2 GEMM + residual(x1) -> d_out
    gemm_tc<3><<<dim3(3, 784), 128, SMEM_TOTAL>>>(h16, w2, fc2B, x1, out, nullptr, CDIM, HIDD);
}